// round 13
// baseline (speedup 1.0000x reference)
#include <cuda_runtime.h>
#include <cuda_bf16.h>
#include <cstdint>

// ---------------------------------------------------------------------------
// Problem constants (B=1)
// ---------------------------------------------------------------------------
#define N_TOK   768
#define DT      447
#define CS      384
#define CZ      128
#define TFD     831           // DT + CS
#define RELD    139           // 66 + 66 + 1 + 6

#define OFF_SINPUT  ((size_t)0)
#define OFF_SINIT   ((size_t)638208)
#define OFF_Z       ((size_t)933120)
#define OFF_REL     ((size_t)76430592)

#define REL_PER_I    (N_TOK * RELD)       // 106752
#define REL_HALF     (REL_PER_I / 2)      // 53376 elements
#define REL_HALF_V4  (REL_HALF / 4)       // 13344 float4

#define KTILES       52                   // ceil(831/16)
#define NCOMBO       1572                 // 792 (td==65) + 780 (rd==32)

// Scratch (device globals: allocation-free)
__device__ __align__(16) float g_ab[2 * N_TOK * CZ];      // a then b
__device__ __align__(16) float g_W12c[NCOMBO * CZ];       // fused rel_enc table

// ---------------------------------------------------------------------------
// packed f32x2 helpers (Blackwell: only reachable via PTX)
// ---------------------------------------------------------------------------
__device__ __forceinline__ uint64_t addx2(uint64_t a, uint64_t b) {
    uint64_t r; asm("add.rn.f32x2 %0, %1, %2;" : "=l"(r) : "l"(a), "l"(b)); return r;
}
__device__ __forceinline__ uint64_t fmax2(uint64_t a, uint64_t b, uint64_t c) {
    uint64_t r; asm("fma.rn.f32x2 %0, %1, %2, %3;" : "=l"(r) : "l"(a), "l"(b), "l"(c)); return r;
}
__device__ __forceinline__ uint64_t bcast2(float x) {
    uint64_t r; unsigned u = __float_as_uint(x);
    asm("mov.b64 %0, {%1, %1};" : "=l"(r) : "r"(u)); return r;
}

union V4 { float4 f; uint64_t u[2]; };

// ---------------------------------------------------------------------------
__device__ __forceinline__ void rel_indices(int ti, int ri, int ai, int ei, int si,
                                            int tj, int rj, int aj, int ej, int sj,
                                            int& rd, int& td, int& cd, int& sent)
{
    const bool sc   = (ai == aj);
    const bool sres = (ri == rj);
    sent = (ei == ej) ? 1 : 0;
    rd = ri - rj + 32; rd = rd < 0 ? 0 : (rd > 64 ? 64 : rd); if (!sc) rd = 65;
    td = ti - tj + 32; td = td < 0 ? 0 : (td > 64 ? 64 : td); if (!(sc && sres)) td = 65;
    cd = si - sj + 2;  cd = cd < 0 ? 0 : (cd > 4  ? 4  : cd); if (!sent) cd = 5;
}

__device__ __forceinline__ int pack_of(int ti, int ri, int ai, int ei, int si,
                                       int tj, int rj, int aj, int ej, int sj)
{
    int rd, td, cd, sent;
    rel_indices(ti, ri, ai, ei, si, tj, rj, aj, ej, sj, rd, td, cd, sent);
    const int tc = sent * 6 + cd;
    return (td == 65) ? (rd * 12 + tc) : (792 + td * 12 + tc);
}

// ---------------------------------------------------------------------------
// rel half-block body (shared by K1 and K2); mask build limited to used rows
// ---------------------------------------------------------------------------
struct RelSmem {
    unsigned int mask[N_TOK * 6];   // 18432 B
    float4 lut[16];
};

__device__ __forceinline__ void rel_body(RelSmem& sh, int i, int h, int tid,
                                         const int* __restrict__ ti_g,
                                         const int* __restrict__ ri_g,
                                         const int* __restrict__ ai_g,
                                         const int* __restrict__ ei_g,
                                         const int* __restrict__ si_g,
                                         float* __restrict__ out)
{
    const int ti = __ldg(ti_g + i), ri = __ldg(ri_g + i), ai = __ldg(ai_g + i);
    const int ei = __ldg(ei_g + i), si = __ldg(si_g + i);

    if (tid < 16) {
        sh.lut[tid] = make_float4((tid & 1) ? 1.f : 0.f,
                                  (tid & 2) ? 1.f : 0.f,
                                  (tid & 4) ? 1.f : 0.f,
                                  (tid & 8) ? 1.f : 0.f);
    }
    // rows actually touched by this half (+1 for crossing access)
    const int j_lo = (h * REL_HALF) / RELD;
    int j_hi = ((h + 1) * REL_HALF - 1) / RELD + 1;
    if (j_hi > N_TOK - 1) j_hi = N_TOK - 1;

    for (int j = j_lo + tid; j <= j_hi; j += 256) {
        int rd, td, cd, sent;
        rel_indices(ti, ri, ai, ei, si,
                    __ldg(ti_g + j), __ldg(ri_g + j), __ldg(ai_g + j),
                    __ldg(ei_g + j), __ldg(si_g + j),
                    rd, td, cd, sent);
        unsigned int m[5] = {0u, 0u, 0u, 0u, 0u};
        m[rd >> 5] |= 1u << (rd & 31);                 // bits 0..65
        const int t2 = 66 + td;                        // bits 66..131
        m[t2 >> 5] |= 1u << (t2 & 31);
        m[4] |= ((unsigned)sent) << 4;                 // bit 132
        m[4] |= 1u << (5 + cd);                        // bits 133..138
        unsigned int* mw = sh.mask + j * 6;
        mw[0] = m[0]; mw[1] = m[1]; mw[2] = m[2];
        mw[3] = m[3]; mw[4] = m[4]; mw[5] = 0u;
    }
    __syncthreads();

    float4* dst = (float4*)(out + OFF_REL + (size_t)i * REL_PER_I) +
                  h * REL_HALF_V4 + tid;
    int lin = h * REL_HALF + tid * 4;
    int j = (int)((unsigned)lin / 139u);
    int t = lin - j * 139;

    for (int k = tid; k < REL_HALF_V4; k += 256) {
        unsigned int bits;
        if (t <= 135) {
            const int base = j * 6 + (t >> 5);
            bits = __funnelshift_r(sh.mask[base], sh.mask[base + 1], t & 31) & 0xFu;
        } else {
            unsigned int a = sh.mask[j * 6 + 4] >> (t - 128);
            unsigned int b = sh.mask[(j + 1) * 6] << (139 - t);
            bits = (a | b) & 0xFu;
        }
        __stcs(dst, sh.lut[bits]);
        dst += 256;
        j += 7; t += 51;
        if (t >= 139) { t -= 139; ++j; }
    }
}

// ===========================================================================
// K1: gemm (240) + combo table (197) + rel halves [0,1344) + s_input (96)
// ===========================================================================
#define K1_GEMM_END  240
#define K1_CMB_END   (K1_GEMM_END + 197)             // 437
#define K1_REL_CNT   1344
#define K1_REL_END   (K1_CMB_END + K1_REL_CNT)       // 1781
#define K1_GRID      (K1_REL_END + 96)               // 1877

__global__ __launch_bounds__(256)
void k1_kernel(const float* __restrict__ tf,
               const float* __restrict__ ta,
               const int* __restrict__ ti_g,
               const int* __restrict__ ri_g,
               const int* __restrict__ ai_g,
               const int* __restrict__ ei_g,
               const int* __restrict__ si_g,
               const float* __restrict__ Wsingle,
               const float* __restrict__ Wleft,
               const float* __restrict__ Wright,
               const float* __restrict__ Wpos,
               float* __restrict__ out)
{
    __shared__ union {
        struct { float As[2][16][68]; float Bs[2][16][36]; } g;   // 13312 B
        RelSmem r;                                                // 18688 B
    } sh;

    const int bx  = blockIdx.x;
    const int tid = threadIdx.x;

    if (bx < K1_GEMM_END) {
        // --------------------- GEMM, double-buffered ---------------------
        const int n0 = (bx / 20) * 64;
        const int c0 = (bx % 20) * 32;
        const int tx = tid & 15;
        const int ty = tid >> 4;
        const int kk = tid & 15;
        const int rl = tid >> 4;

        const float* bpt[2];
#pragma unroll
        for (int p = 0; p < 2; ++p) {
            int gc = c0 + rl + p * 16;
            if (gc < 384)      bpt[p] = Wsingle + (size_t)gc * TFD;
            else if (gc < 512) bpt[p] = Wleft   + (size_t)(gc - 384) * TFD;
            else               bpt[p] = Wright  + (size_t)(gc - 512) * TFD;
        }

        float ra[4], rb[2];
        auto load_tile = [&](int kt) {
            const int kg = kt * 16 + kk;
            const bool kok = (kg < TFD);
#pragma unroll
            for (int p = 0; p < 4; ++p) {
                int n = n0 + rl + p * 16;
                ra[p] = 0.f;
                if (kok)
                    ra[p] = (kg < DT) ? __ldg(tf + (size_t)n * DT + kg)
                                      : __ldg(ta + (size_t)n * CS + (kg - DT));
            }
#pragma unroll
            for (int p = 0; p < 2; ++p)
                rb[p] = kok ? __ldg(bpt[p] + kg) : 0.f;
        };
        auto store_tile = [&](int buf) {
#pragma unroll
            for (int p = 0; p < 4; ++p) sh.g.As[buf][kk][rl + p * 16] = ra[p];
#pragma unroll
            for (int p = 0; p < 2; ++p) sh.g.Bs[buf][kk][rl + p * 16] = rb[p];
        };

        float acc[4][2];
#pragma unroll
        for (int r = 0; r < 4; ++r) { acc[r][0] = 0.f; acc[r][1] = 0.f; }

        load_tile(0);
        store_tile(0);
        __syncthreads();

        for (int kt = 0; kt < KTILES; ++kt) {
            const int cur = kt & 1;
            if (kt + 1 < KTILES) load_tile(kt + 1);
#pragma unroll
            for (int k = 0; k < 16; ++k) {
                float4 av = *(const float4*)&sh.g.As[cur][k][ty * 4];
                float2 bv = *(const float2*)&sh.g.Bs[cur][k][tx * 2];
                acc[0][0] += av.x * bv.x; acc[0][1] += av.x * bv.y;
                acc[1][0] += av.y * bv.x; acc[1][1] += av.y * bv.y;
                acc[2][0] += av.z * bv.x; acc[2][1] += av.z * bv.y;
                acc[3][0] += av.w * bv.x; acc[3][1] += av.w * bv.y;
            }
            if (kt + 1 < KTILES) {
                store_tile(cur ^ 1);
                __syncthreads();
            }
        }

#pragma unroll
        for (int r = 0; r < 4; ++r) {
            int n = n0 + ty * 4 + r;
#pragma unroll
            for (int c = 0; c < 2; ++c) {
                int gc = c0 + tx * 2 + c;
                float v = acc[r][c];
                if (gc < 384)      out[OFF_SINIT + (size_t)n * 384 + gc] = v;
                else if (gc < 512) g_ab[(size_t)n * CZ + (gc - 384)] = v;
                else               g_ab[(size_t)N_TOK * CZ + (size_t)n * CZ + (gc - 512)] = v;
            }
        }
    } else if (bx < K1_CMB_END) {
        // --------------------- fused combo table build -------------------
        const int base = (bx - K1_GEMM_END) * 8;
        const int ch   = tid & 127;
        const float* wr = Wpos + (size_t)ch * RELD;
#pragma unroll
        for (int q = 0; q < 4; ++q) {
            const int c = base + (tid >> 7) + q * 2;
            if (c < NCOMBO) {
                int rd, td, tc;
                if (c < 792) { rd = c / 12; tc = c - rd * 12; td = 65; }
                else { int cc = c - 792; td = cc / 12; tc = cc - td * 12; rd = 32; }
                const int sent = tc / 6;
                const int cd   = tc - sent * 6;
                float v = __ldg(wr + rd) + __ldg(wr + 66 + td) + __ldg(wr + 133 + cd);
                if (sent) v += __ldg(wr + 132);
                g_W12c[(size_t)c * CZ + ch] = v;
            }
        }
    } else if (bx < K1_REL_END) {
        const int idx = bx - K1_CMB_END;         // [0, 1344)
        rel_body(sh.r, idx >> 1, idx & 1, tid, ti_g, ri_g, ai_g, ei_g, si_g, out);
    } else {
        const int n0 = (bx - K1_REL_END) * 8;
        for (int r = 0; r < 8; ++r) {
            const int n = n0 + r;
            float* dst = out + OFF_SINPUT + (size_t)n * TFD;
            const float* srcA = tf + (size_t)n * DT;
            const float* srcB = ta + (size_t)n * CS;
            for (int d = tid; d < DT; d += 256) dst[d] = __ldg(srcA + d);
            for (int d = tid; d < CS; d += 256) dst[DT + d] = __ldg(srcB + d);
        }
    }
}

// ===========================================================================
// K2: i-paired z blocks (768) + rel halves [1344,1536) (192), 4:1 interleave.
//   bx in [0, 960): bx%5==4 -> rel (ridx = 1344 + bx/5)
//                   else    -> z   (zblk = (bx/5)*4 + bx%5  in [0,768))
//   z block: i-pair ip = zblk>>1 (i0=2ip, i1=2ip+1), j-half h = zblk&1.
//   Loads b_j / contact / pack once per j, writes TWO z rows.
// ===========================================================================
#define K2_GRID  960

__global__ __launch_bounds__(256, 6)
void k2_kernel(const float* __restrict__ contact,
               const int* __restrict__ ti_g,
               const int* __restrict__ ri_g,
               const int* __restrict__ ai_g,
               const int* __restrict__ ei_g,
               const int* __restrict__ si_g,
               const float* __restrict__ Wbond,
               float* __restrict__ out)
{
    __shared__ union {
        int pack[2][N_TOK / 2];
        RelSmem r;
    } sh;

    const int bx  = blockIdx.x;
    const int tid = threadIdx.x;
    const int rem = bx % 5;
    const int grp = bx / 5;

    if (rem == 4) {
        const int idx = K1_REL_CNT + grp;        // [1344, 1536)
        rel_body(sh.r, idx >> 1, idx & 1, tid, ti_g, ri_g, ai_g, ei_g, si_g, out);
        return;
    }

    // ------------------------------ z (i-paired) -----------------------
    const int zblk = grp * 4 + rem;              // [0, 768)
    const int ip   = zblk >> 1;
    const int h    = zblk & 1;
    const int i0   = ip * 2;
    const int i1   = i0 + 1;
    const int j0   = h * (N_TOK / 2);
    const int lane = tid & 31;
    const int wid  = tid >> 5;

    const int ti0 = __ldg(ti_g + i0), ri0 = __ldg(ri_g + i0), ai0 = __ldg(ai_g + i0);
    const int ei0 = __ldg(ei_g + i0), si0 = __ldg(si_g + i0);
    const int ti1 = __ldg(ti_g + i1), ri1 = __ldg(ri_g + i1), ai1 = __ldg(ai_g + i1);
    const int ei1 = __ldg(ei_g + i1), si1 = __ldg(si_g + i1);

    for (int jl = tid; jl < N_TOK / 2; jl += 256) {
        const int j = j0 + jl;
        const int tj = __ldg(ti_g + j), rj = __ldg(ri_g + j), aj = __ldg(ai_g + j);
        const int ej = __ldg(ei_g + j), sj = __ldg(si_g + j);
        sh.pack[0][jl] = pack_of(ti0, ri0, ai0, ei0, si0, tj, rj, aj, ej, sj);
        sh.pack[1][jl] = pack_of(ti1, ri1, ai1, ei1, si1, tj, rj, aj, ej, sj);
    }
    __syncthreads();

    const int lane4 = lane * 4;
    V4 a0, a1, bond4;
    a0.f    = *(const float4*)(g_ab + (size_t)i0 * CZ + lane4);
    a1.f    = *(const float4*)(g_ab + (size_t)i1 * CZ + lane4);
    bond4.f = *(const float4*)(Wbond + lane4);

    const float* __restrict__ bmat = g_ab + (size_t)N_TOK * CZ + lane4;
    float* __restrict__ zp0 = out + OFF_Z + (size_t)i0 * N_TOK * CZ +
                              (size_t)(j0 + wid) * CZ + lane4;
    float* __restrict__ zp1 = zp0 + (size_t)N_TOK * CZ;
    const float* __restrict__ crow0 = contact + (size_t)i0 * N_TOK + j0;
    const float* __restrict__ crow1 = crow0 + N_TOK;

#pragma unroll 2
    for (int jl = wid; jl < N_TOK / 2; jl += 8, zp0 += 8 * CZ, zp1 += 8 * CZ) {
        const int p0 = sh.pack[0][jl];
        const int p1 = sh.pack[1][jl];

        V4 w0, w1, b4;
        b4.f = __ldcg((const float4*)(bmat + (size_t)(j0 + jl) * CZ));
        w0.f = __ldg((const float4*)(g_W12c + (size_t)p0 * CZ + lane4));
        w1.f = __ldg((const float4*)(g_W12c + (size_t)p1 * CZ + lane4));
        const uint64_t cm0 = bcast2(__ldcg(crow0 + jl));
        const uint64_t cm1 = bcast2(__ldcg(crow1 + jl));

        V4 z0, z1;
        z0.u[0] = addx2(addx2(w0.u[0], b4.u[0]), fmax2(cm0, bond4.u[0], a0.u[0]));
        z0.u[1] = addx2(addx2(w0.u[1], b4.u[1]), fmax2(cm0, bond4.u[1], a0.u[1]));
        z1.u[0] = addx2(addx2(w1.u[0], b4.u[0]), fmax2(cm1, bond4.u[0], a1.u[0]));
        z1.u[1] = addx2(addx2(w1.u[1], b4.u[1]), fmax2(cm1, bond4.u[1], a1.u[1]));
        __stcs((float4*)zp0, z0.f);
        __stcs((float4*)zp1, z1.f);
    }
}

// ---------------------------------------------------------------------------
// Launch
// ---------------------------------------------------------------------------
extern "C" void kernel_launch(void* const* d_in, const int* in_sizes, int n_in,
                              void* d_out, int out_size)
{
    const float* tf      = (const float*)d_in[0];
    const float* ta      = (const float*)d_in[1];
    const float* contact = (const float*)d_in[2];
    const int*   ti      = (const int*)  d_in[3];
    const int*   ri      = (const int*)  d_in[4];
    const int*   ai      = (const int*)  d_in[5];
    const int*   ei      = (const int*)  d_in[6];
    const int*   si      = (const int*)  d_in[7];
    const float* Wsingle = (const float*)d_in[8];
    const float* Wleft   = (const float*)d_in[9];
    const float* Wright  = (const float*)d_in[10];
    const float* Wpos    = (const float*)d_in[11];
    const float* Wbond   = (const float*)d_in[12];
    float* out = (float*)d_out;

    k1_kernel<<<K1_GRID, 256>>>(tf, ta, ti, ri, ai, ei, si,
                                Wsingle, Wleft, Wright, Wpos, out);

    k2_kernel<<<K2_GRID, 256>>>(contact, ti, ri, ai, ei, si, Wbond, out);
}

// round 14
// speedup vs baseline: 1.0523x; 1.0523x over previous
#include <cuda_runtime.h>
#include <cuda_bf16.h>
#include <cstdint>

// ---------------------------------------------------------------------------
// Problem constants (B=1)
// ---------------------------------------------------------------------------
#define N_TOK   768
#define DT      447
#define CS      384
#define CZ      128
#define TFD     831           // DT + CS
#define RELD    139           // 66 + 66 + 1 + 6

#define OFF_SINPUT  ((size_t)0)
#define OFF_SINIT   ((size_t)638208)
#define OFF_Z       ((size_t)933120)
#define OFF_REL     ((size_t)76430592)

#define REL_PER_I    (N_TOK * RELD)       // 106752
#define REL_HALF     (REL_PER_I / 2)      // 53376 elements
#define REL_HALF_V4  (REL_HALF / 4)       // 13344 float4

#define KTILES       52                   // ceil(831/16)
#define NCOMBO       1572                 // 792 (td==65) + 780 (rd==32)

// Scratch (device globals: allocation-free)
__device__ __align__(16) float g_ab[2 * N_TOK * CZ];      // a then b
__device__ __align__(16) float g_W12c[NCOMBO * CZ];       // fused rel_enc table

// ---------------------------------------------------------------------------
// packed f32x2 helpers (Blackwell: only reachable via PTX)
// ---------------------------------------------------------------------------
__device__ __forceinline__ uint64_t addx2(uint64_t a, uint64_t b) {
    uint64_t r; asm("add.rn.f32x2 %0, %1, %2;" : "=l"(r) : "l"(a), "l"(b)); return r;
}
__device__ __forceinline__ uint64_t fmax2(uint64_t a, uint64_t b, uint64_t c) {
    uint64_t r; asm("fma.rn.f32x2 %0, %1, %2, %3;" : "=l"(r) : "l"(a), "l"(b), "l"(c)); return r;
}
__device__ __forceinline__ uint64_t bcast2(float x) {
    uint64_t r; unsigned u = __float_as_uint(x);
    asm("mov.b64 %0, {%1, %1};" : "=l"(r) : "r"(u)); return r;
}

union V4 { float4 f; uint64_t u[2]; };

// ---------------------------------------------------------------------------
__device__ __forceinline__ void rel_indices(int ti, int ri, int ai, int ei, int si,
                                            int tj, int rj, int aj, int ej, int sj,
                                            int& rd, int& td, int& cd, int& sent)
{
    const bool sc   = (ai == aj);
    const bool sres = (ri == rj);
    sent = (ei == ej) ? 1 : 0;
    rd = ri - rj + 32; rd = rd < 0 ? 0 : (rd > 64 ? 64 : rd); if (!sc) rd = 65;
    td = ti - tj + 32; td = td < 0 ? 0 : (td > 64 ? 64 : td); if (!(sc && sres)) td = 65;
    cd = si - sj + 2;  cd = cd < 0 ? 0 : (cd > 4  ? 4  : cd); if (!sent) cd = 5;
}

__device__ __forceinline__ int pack_of(int ti, int ri, int ai, int ei, int si,
                                       int tj, int rj, int aj, int ej, int sj)
{
    int rd, td, cd, sent;
    rel_indices(ti, ri, ai, ei, si, tj, rj, aj, ej, sj, rd, td, cd, sent);
    const int tc = sent * 6 + cd;
    return (td == 65) ? (rd * 12 + tc) : (792 + td * 12 + tc);
}

// ---------------------------------------------------------------------------
// rel half-block body (shared by K1 and K2); mask build limited to used rows
// ---------------------------------------------------------------------------
struct RelSmem {
    unsigned int mask[N_TOK * 6];   // 18432 B
    float4 lut[16];
};

__device__ __forceinline__ void rel_body(RelSmem& sh, int i, int h, int tid,
                                         const int* __restrict__ ti_g,
                                         const int* __restrict__ ri_g,
                                         const int* __restrict__ ai_g,
                                         const int* __restrict__ ei_g,
                                         const int* __restrict__ si_g,
                                         float* __restrict__ out)
{
    const int ti = __ldg(ti_g + i), ri = __ldg(ri_g + i), ai = __ldg(ai_g + i);
    const int ei = __ldg(ei_g + i), si = __ldg(si_g + i);

    if (tid < 16) {
        sh.lut[tid] = make_float4((tid & 1) ? 1.f : 0.f,
                                  (tid & 2) ? 1.f : 0.f,
                                  (tid & 4) ? 1.f : 0.f,
                                  (tid & 8) ? 1.f : 0.f);
    }
    // rows actually touched by this half (+1 for crossing access)
    const int j_lo = (h * REL_HALF) / RELD;
    int j_hi = ((h + 1) * REL_HALF - 1) / RELD + 1;
    if (j_hi > N_TOK - 1) j_hi = N_TOK - 1;

    for (int j = j_lo + tid; j <= j_hi; j += 256) {
        int rd, td, cd, sent;
        rel_indices(ti, ri, ai, ei, si,
                    __ldg(ti_g + j), __ldg(ri_g + j), __ldg(ai_g + j),
                    __ldg(ei_g + j), __ldg(si_g + j),
                    rd, td, cd, sent);
        unsigned int m[5] = {0u, 0u, 0u, 0u, 0u};
        m[rd >> 5] |= 1u << (rd & 31);                 // bits 0..65
        const int t2 = 66 + td;                        // bits 66..131
        m[t2 >> 5] |= 1u << (t2 & 31);
        m[4] |= ((unsigned)sent) << 4;                 // bit 132
        m[4] |= 1u << (5 + cd);                        // bits 133..138
        unsigned int* mw = sh.mask + j * 6;
        mw[0] = m[0]; mw[1] = m[1]; mw[2] = m[2];
        mw[3] = m[3]; mw[4] = m[4]; mw[5] = 0u;
    }
    __syncthreads();

    float4* dst = (float4*)(out + OFF_REL + (size_t)i * REL_PER_I) +
                  h * REL_HALF_V4 + tid;
    int lin = h * REL_HALF + tid * 4;
    int j = (int)((unsigned)lin / 139u);
    int t = lin - j * 139;

    for (int k = tid; k < REL_HALF_V4; k += 256) {
        unsigned int bits;
        if (t <= 135) {
            const int base = j * 6 + (t >> 5);
            bits = __funnelshift_r(sh.mask[base], sh.mask[base + 1], t & 31) & 0xFu;
        } else {
            unsigned int a = sh.mask[j * 6 + 4] >> (t - 128);
            unsigned int b = sh.mask[(j + 1) * 6] << (139 - t);
            bits = (a | b) & 0xFu;
        }
        __stcs(dst, sh.lut[bits]);
        dst += 256;
        j += 7; t += 51;
        if (t >= 139) { t -= 139; ++j; }
    }
}

// ===========================================================================
// K1: gemm (240) + combo table (197) + rel halves [0,1344) + s_input (96)
// ===========================================================================
#define K1_GEMM_END  240
#define K1_CMB_END   (K1_GEMM_END + 197)             // 437
#define K1_REL_CNT   1344
#define K1_REL_END   (K1_CMB_END + K1_REL_CNT)       // 1781
#define K1_GRID      (K1_REL_END + 96)               // 1877

__global__ __launch_bounds__(256)
void k1_kernel(const float* __restrict__ tf,
               const float* __restrict__ ta,
               const int* __restrict__ ti_g,
               const int* __restrict__ ri_g,
               const int* __restrict__ ai_g,
               const int* __restrict__ ei_g,
               const int* __restrict__ si_g,
               const float* __restrict__ Wsingle,
               const float* __restrict__ Wleft,
               const float* __restrict__ Wright,
               const float* __restrict__ Wpos,
               float* __restrict__ out)
{
    __shared__ union {
        struct { float As[2][16][68]; float Bs[2][16][36]; } g;   // 13312 B
        RelSmem r;                                                // 18688 B
    } sh;

    const int bx  = blockIdx.x;
    const int tid = threadIdx.x;

    if (bx < K1_GEMM_END) {
        // --------------------- GEMM, double-buffered ---------------------
        const int n0 = (bx / 20) * 64;
        const int c0 = (bx % 20) * 32;
        const int tx = tid & 15;
        const int ty = tid >> 4;
        const int kk = tid & 15;
        const int rl = tid >> 4;

        const float* bpt[2];
#pragma unroll
        for (int p = 0; p < 2; ++p) {
            int gc = c0 + rl + p * 16;
            if (gc < 384)      bpt[p] = Wsingle + (size_t)gc * TFD;
            else if (gc < 512) bpt[p] = Wleft   + (size_t)(gc - 384) * TFD;
            else               bpt[p] = Wright  + (size_t)(gc - 512) * TFD;
        }

        float ra[4], rb[2];
        auto load_tile = [&](int kt) {
            const int kg = kt * 16 + kk;
            const bool kok = (kg < TFD);
#pragma unroll
            for (int p = 0; p < 4; ++p) {
                int n = n0 + rl + p * 16;
                ra[p] = 0.f;
                if (kok)
                    ra[p] = (kg < DT) ? __ldg(tf + (size_t)n * DT + kg)
                                      : __ldg(ta + (size_t)n * CS + (kg - DT));
            }
#pragma unroll
            for (int p = 0; p < 2; ++p)
                rb[p] = kok ? __ldg(bpt[p] + kg) : 0.f;
        };
        auto store_tile = [&](int buf) {
#pragma unroll
            for (int p = 0; p < 4; ++p) sh.g.As[buf][kk][rl + p * 16] = ra[p];
#pragma unroll
            for (int p = 0; p < 2; ++p) sh.g.Bs[buf][kk][rl + p * 16] = rb[p];
        };

        float acc[4][2];
#pragma unroll
        for (int r = 0; r < 4; ++r) { acc[r][0] = 0.f; acc[r][1] = 0.f; }

        load_tile(0);
        store_tile(0);
        __syncthreads();

        for (int kt = 0; kt < KTILES; ++kt) {
            const int cur = kt & 1;
            if (kt + 1 < KTILES) load_tile(kt + 1);
#pragma unroll
            for (int k = 0; k < 16; ++k) {
                float4 av = *(const float4*)&sh.g.As[cur][k][ty * 4];
                float2 bv = *(const float2*)&sh.g.Bs[cur][k][tx * 2];
                acc[0][0] += av.x * bv.x; acc[0][1] += av.x * bv.y;
                acc[1][0] += av.y * bv.x; acc[1][1] += av.y * bv.y;
                acc[2][0] += av.z * bv.x; acc[2][1] += av.z * bv.y;
                acc[3][0] += av.w * bv.x; acc[3][1] += av.w * bv.y;
            }
            if (kt + 1 < KTILES) {
                store_tile(cur ^ 1);
                __syncthreads();
            }
        }

#pragma unroll
        for (int r = 0; r < 4; ++r) {
            int n = n0 + ty * 4 + r;
#pragma unroll
            for (int c = 0; c < 2; ++c) {
                int gc = c0 + tx * 2 + c;
                float v = acc[r][c];
                if (gc < 384)      out[OFF_SINIT + (size_t)n * 384 + gc] = v;
                else if (gc < 512) g_ab[(size_t)n * CZ + (gc - 384)] = v;
                else               g_ab[(size_t)N_TOK * CZ + (size_t)n * CZ + (gc - 512)] = v;
            }
        }
    } else if (bx < K1_CMB_END) {
        // --------------------- fused combo table build -------------------
        const int base = (bx - K1_GEMM_END) * 8;
        const int ch   = tid & 127;
        const float* wr = Wpos + (size_t)ch * RELD;
#pragma unroll
        for (int q = 0; q < 4; ++q) {
            const int c = base + (tid >> 7) + q * 2;
            if (c < NCOMBO) {
                int rd, td, tc;
                if (c < 792) { rd = c / 12; tc = c - rd * 12; td = 65; }
                else { int cc = c - 792; td = cc / 12; tc = cc - td * 12; rd = 32; }
                const int sent = tc / 6;
                const int cd   = tc - sent * 6;
                float v = __ldg(wr + rd) + __ldg(wr + 66 + td) + __ldg(wr + 133 + cd);
                if (sent) v += __ldg(wr + 132);
                g_W12c[(size_t)c * CZ + ch] = v;
            }
        }
    } else if (bx < K1_REL_END) {
        const int idx = bx - K1_CMB_END;         // [0, 1344)
        rel_body(sh.r, idx >> 1, idx & 1, tid, ti_g, ri_g, ai_g, ei_g, si_g, out);
    } else {
        const int n0 = (bx - K1_REL_END) * 8;
        for (int r = 0; r < 8; ++r) {
            const int n = n0 + r;
            float* dst = out + OFF_SINPUT + (size_t)n * TFD;
            const float* srcA = tf + (size_t)n * DT;
            const float* srcB = ta + (size_t)n * CS;
            for (int d = tid; d < DT; d += 256) dst[d] = __ldg(srcA + d);
            for (int d = tid; d < CS; d += 256) dst[DT + d] = __ldg(srcB + d);
        }
    }
}

// ===========================================================================
// K2: i-paired z blocks over j-QUARTERS (1536) + rel halves [1344,1536) (192)
//   interleaved 8:1. bx in [0,1728): bx%9==8 -> rel (ridx = 1344 + bx/9)
//                                    else    -> z  (zblk = (bx/9)*8 + bx%9)
//   z block: ip = zblk>>2 (i0=2ip, i1=2ip+1), j-quarter q = zblk&3 (192 j's).
//   Per-block work equals round-12 z blocks; b/contact/pack loaded once per j.
// ===========================================================================
#define K2_GRID  1728
#define N_JQ     (N_TOK / 4)     // 192

__global__ __launch_bounds__(256, 6)
void k2_kernel(const float* __restrict__ contact,
               const int* __restrict__ ti_g,
               const int* __restrict__ ri_g,
               const int* __restrict__ ai_g,
               const int* __restrict__ ei_g,
               const int* __restrict__ si_g,
               const float* __restrict__ Wbond,
               float* __restrict__ out)
{
    __shared__ union {
        int pack[2][N_JQ];
        RelSmem r;
    } sh;

    const int bx  = blockIdx.x;
    const int tid = threadIdx.x;
    const int rem = bx % 9;
    const int grp = bx / 9;

    if (rem == 8) {
        const int idx = K1_REL_CNT + grp;        // [1344, 1536)
        rel_body(sh.r, idx >> 1, idx & 1, tid, ti_g, ri_g, ai_g, ei_g, si_g, out);
        return;
    }

    // ------------------------------ z (i-paired, j-quarter) ------------
    const int zblk = grp * 8 + rem;              // [0, 1536)
    const int ip   = zblk >> 2;
    const int q    = zblk & 3;
    const int i0   = ip * 2;
    const int i1   = i0 + 1;
    const int j0   = q * N_JQ;
    const int lane = tid & 31;
    const int wid  = tid >> 5;

    const int ti0 = __ldg(ti_g + i0), ri0 = __ldg(ri_g + i0), ai0 = __ldg(ai_g + i0);
    const int ei0 = __ldg(ei_g + i0), si0 = __ldg(si_g + i0);
    const int ti1 = __ldg(ti_g + i1), ri1 = __ldg(ri_g + i1), ai1 = __ldg(ai_g + i1);
    const int ei1 = __ldg(ei_g + i1), si1 = __ldg(si_g + i1);

    if (tid < N_JQ) {
        const int j = j0 + tid;
        const int tj = __ldg(ti_g + j), rj = __ldg(ri_g + j), aj = __ldg(ai_g + j);
        const int ej = __ldg(ei_g + j), sj = __ldg(si_g + j);
        sh.pack[0][tid] = pack_of(ti0, ri0, ai0, ei0, si0, tj, rj, aj, ej, sj);
        sh.pack[1][tid] = pack_of(ti1, ri1, ai1, ei1, si1, tj, rj, aj, ej, sj);
    }
    __syncthreads();

    const int lane4 = lane * 4;
    V4 a0, a1, bond4;
    a0.f    = *(const float4*)(g_ab + (size_t)i0 * CZ + lane4);
    a1.f    = *(const float4*)(g_ab + (size_t)i1 * CZ + lane4);
    bond4.f = *(const float4*)(Wbond + lane4);

    const float* __restrict__ bmat = g_ab + (size_t)N_TOK * CZ + lane4;
    float* __restrict__ zp0 = out + OFF_Z + (size_t)i0 * N_TOK * CZ +
                              (size_t)(j0 + wid) * CZ + lane4;
    float* __restrict__ zp1 = zp0 + (size_t)N_TOK * CZ;
    const float* __restrict__ crow0 = contact + (size_t)i0 * N_TOK + j0;
    const float* __restrict__ crow1 = crow0 + N_TOK;

#pragma unroll 2
    for (int jl = wid; jl < N_JQ; jl += 8, zp0 += 8 * CZ, zp1 += 8 * CZ) {
        const int p0 = sh.pack[0][jl];
        const int p1 = sh.pack[1][jl];

        V4 w0, w1, b4;
        b4.f = __ldcg((const float4*)(bmat + (size_t)(j0 + jl) * CZ));
        w0.f = __ldg((const float4*)(g_W12c + (size_t)p0 * CZ + lane4));
        w1.f = __ldg((const float4*)(g_W12c + (size_t)p1 * CZ + lane4));
        const uint64_t cm0 = bcast2(__ldcg(crow0 + jl));
        const uint64_t cm1 = bcast2(__ldcg(crow1 + jl));

        V4 z0, z1;
        z0.u[0] = addx2(addx2(w0.u[0], b4.u[0]), fmax2(cm0, bond4.u[0], a0.u[0]));
        z0.u[1] = addx2(addx2(w0.u[1], b4.u[1]), fmax2(cm0, bond4.u[1], a0.u[1]));
        z1.u[0] = addx2(addx2(w1.u[0], b4.u[0]), fmax2(cm1, bond4.u[0], a1.u[0]));
        z1.u[1] = addx2(addx2(w1.u[1], b4.u[1]), fmax2(cm1, bond4.u[1], a1.u[1]));
        __stcs((float4*)zp0, z0.f);
        __stcs((float4*)zp1, z1.f);
    }
}

// ---------------------------------------------------------------------------
// Launch
// ---------------------------------------------------------------------------
extern "C" void kernel_launch(void* const* d_in, const int* in_sizes, int n_in,
                              void* d_out, int out_size)
{
    const float* tf      = (const float*)d_in[0];
    const float* ta      = (const float*)d_in[1];
    const float* contact = (const float*)d_in[2];
    const int*   ti      = (const int*)  d_in[3];
    const int*   ri      = (const int*)  d_in[4];
    const int*   ai      = (const int*)  d_in[5];
    const int*   ei      = (const int*)  d_in[6];
    const int*   si      = (const int*)  d_in[7];
    const float* Wsingle = (const float*)d_in[8];
    const float* Wleft   = (const float*)d_in[9];
    const float* Wright  = (const float*)d_in[10];
    const float* Wpos    = (const float*)d_in[11];
    const float* Wbond   = (const float*)d_in[12];
    float* out = (float*)d_out;

    k1_kernel<<<K1_GRID, 256>>>(tf, ta, ti, ri, ai, ei, si,
                                Wsingle, Wleft, Wright, Wpos, out);

    k2_kernel<<<K2_GRID, 256>>>(contact, ti, ri, ai, ei, si, Wbond, out);
}